// round 1
// baseline (speedup 1.0000x reference)
#include <cuda_runtime.h>
#include <cstdint>
#include <cstddef>

// Xonv2D: out[b,o,h,w] = sum_{c,kh,kw} x[b,c,h+kh-1,w+kw-1] * W[h,w,o,c,kh,kw] + bias[h,w,o]
// B=4, CIN=COUT=16, K=3, H=W=128.
// Weights = 151 MB streamed once -> pure HBM-bound. Stage weights via 1D bulk TMA
// (contiguous per-pixel 9216B records) into smem, double buffered.

static constexpr int Hc = 128, Wc = 128, CINc = 16, COUTc = 16, Bc = 4;
static constexpr int PX_PER_BLOCK = 8;        // pixels (same h, consecutive w) per block
static constexpr int PX_PER_CHUNK = 4;        // pixels per TMA chunk
static constexpr int FLOATS_PER_PX = COUTc * CINc * 9;          // 2304
static constexpr int CHUNK_FLOATS  = PX_PER_CHUNK * FLOATS_PER_PX; // 9216
static constexpr int CHUNK_BYTES   = CHUNK_FLOATS * 4;             // 36864
static constexpr int WT = PX_PER_BLOCK + 2;   // x tile cols (halo)  = 10
static constexpr int XC_STRIDE = 122;         // floats per c in x tile (3*WT*4=120, +2 pad: even + bank-spread)
static constexpr int SMEM_X_OFF   = 2 * CHUNK_BYTES;                   // 73728
static constexpr int SMEM_X_BYTES = CINc * XC_STRIDE * 4;              // 7808
static constexpr int SMEM_MBAR_OFF = SMEM_X_OFF + SMEM_X_BYTES;        // 81536
static constexpr int SMEM_TOTAL    = SMEM_MBAR_OFF + 16;               // 81552

__device__ __forceinline__ uint32_t smem_u32(const void* p) {
    return (uint32_t)__cvta_generic_to_shared(p);
}

__device__ __forceinline__ void mbar_init(uint32_t a, uint32_t count) {
    asm volatile("mbarrier.init.shared.b64 [%0], %1;" :: "r"(a), "r"(count) : "memory");
}
__device__ __forceinline__ void mbar_expect_tx(uint32_t a, uint32_t bytes) {
    asm volatile("mbarrier.arrive.expect_tx.shared.b64 _, [%0], %1;" :: "r"(a), "r"(bytes) : "memory");
}
__device__ __forceinline__ void tma_bulk_g2s(uint32_t dst, const void* src, uint32_t bytes, uint32_t mbar) {
    asm volatile("cp.async.bulk.shared::cta.global.mbarrier::complete_tx::bytes [%0], [%1], %2, [%3];"
                 :: "r"(dst), "l"(src), "r"(bytes), "r"(mbar) : "memory");
}
__device__ __forceinline__ void mbar_wait(uint32_t a, uint32_t parity) {
    uint32_t done;
    asm volatile(
        "{\n\t.reg .pred p;\n\t"
        "mbarrier.try_wait.parity.acquire.cta.shared::cta.b64 p, [%1], %2;\n\t"
        "selp.b32 %0, 1, 0, p;\n\t}"
        : "=r"(done) : "r"(a), "r"(parity) : "memory");
    while (!done) {
        asm volatile(
            "{\n\t.reg .pred p;\n\t"
            "mbarrier.try_wait.parity.acquire.cta.shared::cta.b64 p, [%1], %2, 0x989680;\n\t"
            "selp.b32 %0, 1, 0, p;\n\t}"
            : "=r"(done) : "r"(a), "r"(parity) : "memory");
    }
}

__global__ void __launch_bounds__(128, 2)
xonv2d_kernel(const float* __restrict__ x,
              const float* __restrict__ wts,
              const float* __restrict__ bias,
              float* __restrict__ out)
{
    extern __shared__ char smem[];
    float* swt = reinterpret_cast<float*>(smem);                    // 2 weight chunks
    float* sx  = reinterpret_cast<float*>(smem + SMEM_X_OFF);       // x tile [c][ (r*WT+col)*4 + b ]
    const uint32_t mbar0 = smem_u32(smem + SMEM_MBAR_OFF);
    const uint32_t mbar1 = mbar0 + 8;

    const int t   = threadIdx.x;
    const int bid = blockIdx.x;
    const int h   = bid >> 4;                 // 16 blocks per row (128/8)
    const int w0  = (bid & 15) * PX_PER_BLOCK;

    if (t == 0) {
        mbar_init(mbar0, 1);
        mbar_init(mbar1, 1);
    }
    __syncthreads();

    if (t == 0) {
        const float* src = wts + (size_t)(h * Wc + w0) * FLOATS_PER_PX;
        mbar_expect_tx(mbar0, CHUNK_BYTES);
        tma_bulk_g2s(smem_u32(swt), src, CHUNK_BYTES, mbar0);
        mbar_expect_tx(mbar1, CHUNK_BYTES);
        tma_bulk_g2s(smem_u32(swt + CHUNK_FLOATS), src + CHUNK_FLOATS, CHUNK_BYTES, mbar1);
    }

    // ---- load x tile into shared: sx[c*XC_STRIDE + (r*WT+col)*4 + b], zero-padded halo ----
    // 4b * 16c * 3r * 10col = 1920 elements, col fastest for coalesced-ish global reads.
    for (int idx = t; idx < Bc * CINc * 3 * WT; idx += 128) {
        int col = idx % WT;
        int r   = (idx / WT) % 3;
        int c   = (idx / (WT * 3)) % CINc;
        int b   = idx / (WT * 3 * CINc);
        int hh  = h - 1 + r;
        int ww  = w0 - 1 + col;
        float v = 0.0f;
        if (hh >= 0 && hh < Hc && ww >= 0 && ww < Wc)
            v = x[(((size_t)(b * CINc + c)) * Hc + hh) * Wc + ww];
        sx[c * XC_STRIDE + (r * WT + col) * 4 + b] = v;
    }
    __syncthreads();

    // thread decomposition: bh = batch pair, jh = j-quarter (= 4 input channels),
    // og = output-channel group of 4, px = pixel within 4-pixel group
    const int bh = t & 1;
    const int jh = (t >> 1) & 3;
    const int og = (t >> 3) & 3;
    const int px = t >> 5;

    const float* xbase = sx + (jh * 4) * XC_STRIDE + bh * 2;  // + (col)*4 added per access

    #pragma unroll
    for (int g = 0; g < 2; g++) {
        mbar_wait(g == 0 ? mbar0 : mbar1, 0);

        const float* wb = swt + g * CHUNK_FLOATS + px * FLOATS_PER_PX + og * (4 * 144) + jh * 36;
        const float* xg = xbase + (g * PX_PER_CHUNK + px) * 4;

        float acc[4][2];
        #pragma unroll
        for (int oo = 0; oo < 4; oo++) { acc[oo][0] = 0.0f; acc[oo][1] = 0.0f; }

        #pragma unroll
        for (int i4 = 0; i4 < 9; i4++) {
            float4 wv[4];
            #pragma unroll
            for (int oo = 0; oo < 4; oo++)
                wv[oo] = *reinterpret_cast<const float4*>(wb + oo * 144 + i4 * 4);

            #pragma unroll
            for (int k = 0; k < 4; k++) {
                const int j  = i4 * 4 + k;          // 0..35 within this jh quarter
                const int dc = j / 9;               // compile-time
                const int rs = j % 9;
                const int r  = rs / 3;
                const int s  = rs % 3;
                float2 xv = *reinterpret_cast<const float2*>(xg + dc * XC_STRIDE + (r * WT + s) * 4);
                const float w0f = (k == 0) ? wv[0].x : (k == 1) ? wv[0].y : (k == 2) ? wv[0].z : wv[0].w;
                const float w1f = (k == 0) ? wv[1].x : (k == 1) ? wv[1].y : (k == 2) ? wv[1].z : wv[1].w;
                const float w2f = (k == 0) ? wv[2].x : (k == 1) ? wv[2].y : (k == 2) ? wv[2].z : wv[2].w;
                const float w3f = (k == 0) ? wv[3].x : (k == 1) ? wv[3].y : (k == 2) ? wv[3].z : wv[3].w;
                acc[0][0] += w0f * xv.x;  acc[0][1] += w0f * xv.y;
                acc[1][0] += w1f * xv.x;  acc[1][1] += w1f * xv.y;
                acc[2][0] += w2f * xv.x;  acc[2][1] += w2f * xv.y;
                acc[3][0] += w3f * xv.x;  acc[3][1] += w3f * xv.y;
            }
        }

        // reduce the jh quarters (lane bits 1,2)
        #pragma unroll
        for (int oo = 0; oo < 4; oo++) {
            #pragma unroll
            for (int bb = 0; bb < 2; bb++) {
                float v = acc[oo][bb];
                v += __shfl_xor_sync(0xffffffffu, v, 2);
                v += __shfl_xor_sync(0xffffffffu, v, 4);
                acc[oo][bb] = v;
            }
        }

        if (jh == 0) {
            const int wglob = w0 + g * PX_PER_CHUNK + px;
            const float4 bv = *reinterpret_cast<const float4*>(
                bias + ((size_t)(h * Wc + wglob) * COUTc + og * 4));
            #pragma unroll
            for (int oo = 0; oo < 4; oo++) {
                const int o  = og * 4 + oo;
                const float bs = (oo == 0) ? bv.x : (oo == 1) ? bv.y : (oo == 2) ? bv.z : bv.w;
                #pragma unroll
                for (int bb = 0; bb < 2; bb++) {
                    const int b = bh * 2 + bb;
                    out[(((size_t)(b * COUTc + o)) * Hc + h) * Wc + wglob] = acc[oo][bb] + bs;
                }
            }
        }
    }
}

extern "C" void kernel_launch(void* const* d_in, const int* in_sizes, int n_in,
                              void* d_out, int out_size) {
    const float* x    = (const float*)d_in[0];
    const float* wts  = (const float*)d_in[1];
    const float* bias = (const float*)d_in[2];
    float* out        = (float*)d_out;

    cudaFuncSetAttribute(xonv2d_kernel, cudaFuncAttributeMaxDynamicSharedMemorySize, SMEM_TOTAL);

    const int grid = (Hc * Wc) / PX_PER_BLOCK;   // 2048 blocks
    xonv2d_kernel<<<grid, 128, SMEM_TOTAL>>>(x, wts, bias, out);
}

// round 2
// speedup vs baseline: 1.4140x; 1.4140x over previous
#include <cuda_runtime.h>
#include <cstdint>
#include <cstddef>

// Xonv2D: out[b,o,h,w] = sum_{c,kh,kw} x[b,c,h+kh-1,w+kw-1] * W[h,w,o,c,kh,kw] + bias[h,w,o]
// B=4, CIN=COUT=16, K=3, H=W=128.  Weights = 151MB streamed once -> HBM-bound.
// Persistent CTAs + 3-deep TMA ring so weight loads are ALWAYS in flight.
// x (4MB, L2-resident) read directly via __ldg; no x staging, no serial prologue.

static constexpr int Hc = 128, Wc = 128;
static constexpr int GROUPS = 4096;                 // 4-pixel groups (128*128/4)
static constexpr int RING = 3;
static constexpr int FLOATS_PER_PX = 16 * 16 * 9;   // 2304
static constexpr int CHUNK_FLOATS  = 4 * FLOATS_PER_PX;  // 9216 (4 pixels)
static constexpr int CHUNK_BYTES   = CHUNK_FLOATS * 4;   // 36864
static constexpr int SMEM_MBAR_OFF = RING * CHUNK_BYTES; // 110592
static constexpr int SMEM_TOTAL    = SMEM_MBAR_OFF + RING * 8 + 8;
static constexpr int GRID          = 304;           // ~2 CTAs/SM on GB300 (152 SMs)

__device__ __forceinline__ uint32_t smem_u32(const void* p) {
    return (uint32_t)__cvta_generic_to_shared(p);
}
__device__ __forceinline__ void mbar_init(uint32_t a, uint32_t count) {
    asm volatile("mbarrier.init.shared.b64 [%0], %1;" :: "r"(a), "r"(count) : "memory");
}
__device__ __forceinline__ void mbar_expect_tx(uint32_t a, uint32_t bytes) {
    asm volatile("mbarrier.arrive.expect_tx.shared.b64 _, [%0], %1;" :: "r"(a), "r"(bytes) : "memory");
}
__device__ __forceinline__ void tma_bulk_g2s(uint32_t dst, const void* src, uint32_t bytes, uint32_t mbar) {
    asm volatile("cp.async.bulk.shared::cta.global.mbarrier::complete_tx::bytes [%0], [%1], %2, [%3];"
                 :: "r"(dst), "l"(src), "r"(bytes), "r"(mbar) : "memory");
}
__device__ __forceinline__ void mbar_wait(uint32_t a, uint32_t parity) {
    uint32_t done;
    asm volatile(
        "{\n\t.reg .pred p;\n\t"
        "mbarrier.try_wait.parity.acquire.cta.shared::cta.b64 p, [%1], %2;\n\t"
        "selp.b32 %0, 1, 0, p;\n\t}"
        : "=r"(done) : "r"(a), "r"(parity) : "memory");
    while (!done) {
        asm volatile(
            "{\n\t.reg .pred p;\n\t"
            "mbarrier.try_wait.parity.acquire.cta.shared::cta.b64 p, [%1], %2, 0x989680;\n\t"
            "selp.b32 %0, 1, 0, p;\n\t}"
            : "=r"(done) : "r"(a), "r"(parity) : "memory");
    }
}

__global__ void __launch_bounds__(128, 2)
xonv2d_kernel(const float* __restrict__ x,
              const float* __restrict__ wts,
              const float* __restrict__ bias,
              float* __restrict__ out)
{
    extern __shared__ char smem[];
    float* swt = reinterpret_cast<float*>(smem);
    const uint32_t mb = smem_u32(smem + SMEM_MBAR_OFF);

    const int t   = threadIdx.x;
    const int bid = blockIdx.x;

    if (t == 0) {
        #pragma unroll
        for (int s = 0; s < RING; s++) mbar_init(mb + s * 8, 1);
    }
    __syncthreads();

    // Prologue: fill RING-1 slots.
    if (t == 0) {
        #pragma unroll
        for (int j = 0; j < RING - 1; j++) {
            int gi = bid + j * GRID;
            if (gi < GROUPS) {
                mbar_expect_tx(mb + j * 8, CHUNK_BYTES);
                tma_bulk_g2s(smem_u32(swt + j * CHUNK_FLOATS),
                             wts + (size_t)gi * CHUNK_FLOATS, CHUNK_BYTES, mb + j * 8);
            }
        }
    }

    // Thread decomposition: bh(bit0)=batch pair, jh(bits1-2)=cin quarter,
    // og(bits3-4)=cout group of 4, px(bits5-6)=pixel within group.
    const int bh = t & 1;
    const int jh = (t >> 1) & 3;
    const int og = (t >> 3) & 3;
    const int px = t >> 5;

    for (int j = 0, gi = bid; gi < GROUPS; j++, gi += GRID) {
        const int slot   = j % RING;
        const int parity = (j / RING) & 1;

        mbar_wait(mb + slot * 8, parity);
        __syncthreads();   // everyone finished reading slot (j-1) -> its smem (== slot j+2) reusable

        if (t == 0) {
            int gn = gi + (RING - 1) * GRID;
            if (gn < GROUPS) {
                int sn = (j + RING - 1) % RING;
                mbar_expect_tx(mb + sn * 8, CHUNK_BYTES);
                tma_bulk_g2s(smem_u32(swt + sn * CHUNK_FLOATS),
                             wts + (size_t)gn * CHUNK_FLOATS, CHUNK_BYTES, mb + sn * 8);
            }
        }

        const int pix = gi * 4 + px;
        const int h   = pix >> 7;
        const int w   = pix & 127;

        // Row/col validity for the 3x3 halo (r,s are compile-time below).
        const bool mr0 = (h > 0), mr2 = (h < Hc - 1);
        const bool ms0 = (w > 0), ms2 = (w < Wc - 1);

        // x base for (b = bh*2, c = jh*4), positioned at (h-1, w-1)
        const float* xb = x + (((size_t)(bh * 2 * 16 + jh * 4) * Hc + (h - 1)) * Wc + (w - 1));
        const float* wb = swt + slot * CHUNK_FLOATS + px * FLOATS_PER_PX + og * 576 + jh * 36;

        float acc[4][2];
        #pragma unroll
        for (int oo = 0; oo < 4; oo++) { acc[oo][0] = 0.0f; acc[oo][1] = 0.0f; }

        #pragma unroll
        for (int i4 = 0; i4 < 9; i4++) {
            float4 wv[4];
            #pragma unroll
            for (int oo = 0; oo < 4; oo++)
                wv[oo] = *reinterpret_cast<const float4*>(wb + oo * 144 + i4 * 4);

            #pragma unroll
            for (int k = 0; k < 4; k++) {
                const int jj = i4 * 4 + k;        // 0..35
                const int dc = jj / 9;
                const int rs = jj % 9;
                const int r  = rs / 3;
                const int s  = rs % 3;
                const bool ok = (r == 0 ? mr0 : (r == 2 ? mr2 : true)) &&
                                (s == 0 ? ms0 : (s == 2 ? ms2 : true));
                const size_t off = (size_t)dc * (Hc * Wc) + r * Wc + s;
                const float xv0 = ok ? __ldg(xb + off)                     : 0.0f;
                const float xv1 = ok ? __ldg(xb + off + 16 * Hc * Wc)      : 0.0f;
                const float w0f = (k == 0) ? wv[0].x : (k == 1) ? wv[0].y : (k == 2) ? wv[0].z : wv[0].w;
                const float w1f = (k == 0) ? wv[1].x : (k == 1) ? wv[1].y : (k == 2) ? wv[1].z : wv[1].w;
                const float w2f = (k == 0) ? wv[2].x : (k == 1) ? wv[2].y : (k == 2) ? wv[2].z : wv[2].w;
                const float w3f = (k == 0) ? wv[3].x : (k == 1) ? wv[3].y : (k == 2) ? wv[3].z : wv[3].w;
                acc[0][0] += w0f * xv0;  acc[0][1] += w0f * xv1;
                acc[1][0] += w1f * xv0;  acc[1][1] += w1f * xv1;
                acc[2][0] += w2f * xv0;  acc[2][1] += w2f * xv1;
                acc[3][0] += w3f * xv0;  acc[3][1] += w3f * xv1;
            }
        }

        // Reduce the 4 jh quarters (lane bits 1,2).
        #pragma unroll
        for (int oo = 0; oo < 4; oo++) {
            #pragma unroll
            for (int bb = 0; bb < 2; bb++) {
                float v = acc[oo][bb];
                v += __shfl_xor_sync(0xffffffffu, v, 2);
                v += __shfl_xor_sync(0xffffffffu, v, 4);
                acc[oo][bb] = v;
            }
        }

        if (jh == 0) {
            const float4 bv = *reinterpret_cast<const float4*>(
                bias + ((size_t)pix * 16 + og * 4));
            #pragma unroll
            for (int oo = 0; oo < 4; oo++) {
                const int o   = og * 4 + oo;
                const float bs = (oo == 0) ? bv.x : (oo == 1) ? bv.y : (oo == 2) ? bv.z : bv.w;
                #pragma unroll
                for (int bb = 0; bb < 2; bb++) {
                    const int b = bh * 2 + bb;
                    out[(((size_t)(b * 16 + o)) * Hc + h) * Wc + w] = acc[oo][bb] + bs;
                }
            }
        }
    }
}

extern "C" void kernel_launch(void* const* d_in, const int* in_sizes, int n_in,
                              void* d_out, int out_size) {
    const float* x    = (const float*)d_in[0];
    const float* wts  = (const float*)d_in[1];
    const float* bias = (const float*)d_in[2];
    float* out        = (float*)d_out;

    cudaFuncSetAttribute(xonv2d_kernel, cudaFuncAttributeMaxDynamicSharedMemorySize, SMEM_TOTAL);
    xonv2d_kernel<<<GRID, 128, SMEM_TOTAL>>>(x, wts, bias, out);
}